// round 1
// baseline (speedup 1.0000x reference)
#include <cuda_runtime.h>

// PinnWithGRU: B=2048 sequences, T=2048 steps, D=3 input, H=32 hidden.
// One warp per sequence, one hidden unit per lane. W_hh rows in registers.
#define BB 2048
#define TT 2048
#define DD 3
#define HH 32

__device__ __forceinline__ float sigmoid_fast(float x) {
    // 1 / (1 + e^-x) via MUFU.EX2 + MUFU.RCP (~2 ulp)
    return __fdividef(1.0f, 1.0f + __expf(-x));
}
__device__ __forceinline__ float tanh_fast(float x) {
    // 2/(1+e^-2x) - 1 via MUFU.EX2 + MUFU.RCP (~2 ulp)
    return __fdividef(2.0f, 1.0f + __expf(-2.0f * x)) - 1.0f;
}

__global__ __launch_bounds__(64)
void gru_scan_kernel(const float* __restrict__ inp,     // [B, T, 3]
                     const float* __restrict__ Wih,     // [96, 3]
                     const float* __restrict__ Whh,     // [96, 32]
                     const float* __restrict__ bias,    // [96]
                     const float* __restrict__ bias_n,  // [32]
                     float* __restrict__ out)           // [B, T]
{
    const int lane = threadIdx.x & 31;
    const int b    = (blockIdx.x * blockDim.x + threadIdx.x) >> 5;
    if (b >= BB) return;

    // --- Per-lane weights: row (g*32+lane) of W_hh for each gate, in registers ---
    float wr[HH], wz[HH], wa[HH];
    const float4* whh4 = reinterpret_cast<const float4*>(Whh);
    #pragma unroll
    for (int k4 = 0; k4 < HH / 4; k4++) {
        float4 v;
        v = whh4[(0 * HH + lane) * (HH / 4) + k4];
        wr[4*k4+0] = v.x; wr[4*k4+1] = v.y; wr[4*k4+2] = v.z; wr[4*k4+3] = v.w;
        v = whh4[(1 * HH + lane) * (HH / 4) + k4];
        wz[4*k4+0] = v.x; wz[4*k4+1] = v.y; wz[4*k4+2] = v.z; wz[4*k4+3] = v.w;
        v = whh4[(2 * HH + lane) * (HH / 4) + k4];
        wa[4*k4+0] = v.x; wa[4*k4+1] = v.y; wa[4*k4+2] = v.z; wa[4*k4+3] = v.w;
    }

    // Input-gate weights (rows of [96,3]) and biases for this lane
    const float wir0 = Wih[(0*HH + lane)*DD + 0];
    const float wir1 = Wih[(0*HH + lane)*DD + 1];
    const float wir2 = Wih[(0*HH + lane)*DD + 2];
    const float wiz0 = Wih[(1*HH + lane)*DD + 0];
    const float wiz1 = Wih[(1*HH + lane)*DD + 1];
    const float wiz2 = Wih[(1*HH + lane)*DD + 2];
    const float wia0 = Wih[(2*HH + lane)*DD + 0];
    const float wia1 = Wih[(2*HH + lane)*DD + 1];
    const float wia2 = Wih[(2*HH + lane)*DD + 2];
    const float br = bias[0*HH + lane];
    const float bz = bias[1*HH + lane];
    const float ba = bias[2*HH + lane] + bias_n[lane];  // fold bias_n into candidate bias

    const float* __restrict__ xp = inp + (size_t)b * TT * DD;
    float*       __restrict__ op = out + (size_t)b * TT;

    float h = 0.0f;

    // Prefetch first step's x (uniform across the warp -> broadcast load)
    float x0 = xp[0], x1 = xp[1], x2 = xp[2];

    float4 obuf;  // lane 0 buffers 4 outputs, stores as float4

    for (int t = 0; t < TT; t++) {
        // Prefetch next step's x to hide L2 latency behind this step's compute
        const int tn = (t + 1 < TT) ? (t + 1) : t;
        const float nx0 = xp[tn * DD + 0];
        const float nx1 = xp[tn * DD + 1];
        const float nx2 = xp[tn * DD + 2];

        // Input gates (biases folded in)
        float ir = fmaf(wir2, x2, fmaf(wir1, x1, fmaf(wir0, x0, br)));
        float iz = fmaf(wiz2, x2, fmaf(wiz1, x1, fmaf(wiz0, x0, bz)));
        float ia = fmaf(wia2, x2, fmaf(wia1, x1, fmaf(wia0, x0, ba)));

        // Hidden gates: hg[lane] = sum_k W_hh[g*32+lane, k] * h[k]
        float hr = 0.0f, hz = 0.0f, ha = 0.0f;
        #pragma unroll
        for (int k = 0; k < HH; k++) {
            const float hk = __shfl_sync(0xffffffffu, h, k);
            hr = fmaf(wr[k], hk, hr);
            hz = fmaf(wz[k], hk, hz);
            ha = fmaf(wa[k], hk, ha);
        }

        const float r = sigmoid_fast(ir + hr);
        const float z = sigmoid_fast(iz + hz);
        const float n = tanh_fast(fmaf(r, ha, ia));

        // h_new = (1-z)*n + z*h = n + z*(h-n)
        h = fmaf(z, h - n, n);

        // Emit h[0]: lane 0 buffers 4 steps and stores a float4
        if (lane == 0) {
            const int q = t & 3;
            if (q == 0) obuf.x = h;
            else if (q == 1) obuf.y = h;
            else if (q == 2) obuf.z = h;
            else {
                obuf.w = h;
                *reinterpret_cast<float4*>(op + (t - 3)) = obuf;
            }
        }

        x0 = nx0; x1 = nx1; x2 = nx2;
    }
}

extern "C" void kernel_launch(void* const* d_in, const int* in_sizes, int n_in,
                              void* d_out, int out_size) {
    const float* inp    = (const float*)d_in[0];
    const float* wih    = (const float*)d_in[1];
    const float* whh    = (const float*)d_in[2];
    const float* bias   = (const float*)d_in[3];
    const float* bias_n = (const float*)d_in[4];
    float* out = (float*)d_out;

    // 2048 warps total: 64 threads/block (2 warps) x 1024 blocks
    gru_scan_kernel<<<BB / 2, 64>>>(inp, wih, whh, bias, bias_n, out);
}

// round 5
// speedup vs baseline: 2.1852x; 2.1852x over previous
#include <cuda_runtime.h>

// PinnWithGRU: B=2048 sequences, T=2048 steps, D=3 input, H=32 hidden.
// One warp per sequence, one hidden unit per lane. W_hh rows in registers.
// h broadcast via per-warp double-buffered SMEM + LDS.128 (all lanes same addr
// -> broadcast wavefront), replacing 32 SHFLs per step.
#define BB 2048
#define TT 2048
#define DD 3
#define HH 32

__device__ __forceinline__ float sigmoid_fast(float x) {
    return __fdividef(1.0f, 1.0f + __expf(-x));   // MUFU.EX2 + MUFU.RCP
}
__device__ __forceinline__ float tanh_fast(float x) {
    return __fdividef(2.0f, 1.0f + __expf(-2.0f * x)) - 1.0f;
}

struct GruW {
    float wr[HH], wz[HH], wa[HH];
    float wir0, wir1, wir2, wiz0, wiz1, wiz2, wia0, wia1, wia2;
    float br, bz, ba;
};

// One GRU step. h broadcast through wbuf (this step's buffer); rbuf is unused
// this step (double buffer handled by caller alternation).
__device__ __forceinline__ float gru_step(float h, float x0, float x1, float x2,
                                          const GruW& W,
                                          float* __restrict__ wbuf, int lane) {
    // Input gates seeded into the accumulators (biases folded)
    float ar0 = fmaf(W.wir2, x2, fmaf(W.wir1, x1, fmaf(W.wir0, x0, W.br)));
    float az0 = fmaf(W.wiz2, x2, fmaf(W.wiz1, x1, fmaf(W.wiz0, x0, W.bz)));
    float aa0 = fmaf(W.wia2, x2, fmaf(W.wia1, x1, fmaf(W.wia0, x0, W.ba)));
    float ar1 = 0.0f, az1 = 0.0f, aa1 = 0.0f;

    wbuf[lane] = h;
    __syncwarp();
    const float4* hb = reinterpret_cast<const float4*>(wbuf);

    #pragma unroll
    for (int k4 = 0; k4 < HH / 4; k4++) {
        const float4 hv = hb[k4];           // broadcast LDS.128
        ar0 = fmaf(W.wr[4*k4+0], hv.x, ar0);
        ar1 = fmaf(W.wr[4*k4+1], hv.y, ar1);
        ar0 = fmaf(W.wr[4*k4+2], hv.z, ar0);
        ar1 = fmaf(W.wr[4*k4+3], hv.w, ar1);
        az0 = fmaf(W.wz[4*k4+0], hv.x, az0);
        az1 = fmaf(W.wz[4*k4+1], hv.y, az1);
        az0 = fmaf(W.wz[4*k4+2], hv.z, az0);
        az1 = fmaf(W.wz[4*k4+3], hv.w, az1);
        aa0 = fmaf(W.wa[4*k4+0], hv.x, aa0);
        aa1 = fmaf(W.wa[4*k4+1], hv.y, aa1);
        aa0 = fmaf(W.wa[4*k4+2], hv.z, aa0);
        aa1 = fmaf(W.wa[4*k4+3], hv.w, aa1);
    }

    const float r = sigmoid_fast(ar0 + ar1);
    const float z = sigmoid_fast(az0 + az1);
    const float n = tanh_fast(fmaf(r, aa0 + aa1, 0.0f) + 0.0f * r  // keep shape
                              );
    // NOTE: candidate is tanh(ia + ba + r*ha); ia+ba folded into aa0 seed,
    // but r multiplies ONLY the hidden part (aa0+aa1 minus the seed)!  -> fix below.
    (void)n;
    return 0.0f; // unreachable placeholder (specialized version used instead)
}

__global__ __launch_bounds__(64, 7)
void gru_scan_kernel(const float* __restrict__ inp,     // [B, T, 3]
                     const float* __restrict__ Wih,     // [96, 3]
                     const float* __restrict__ Whh,     // [96, 32]
                     const float* __restrict__ bias,    // [96]
                     const float* __restrict__ bias_n,  // [32]
                     float* __restrict__ out)           // [B, T]
{
    const int lane = threadIdx.x & 31;
    const int wid  = (threadIdx.x >> 5);                 // warp in block (0..1)
    const int b    = blockIdx.x * 2 + wid;
    if (b >= BB) return;

    __shared__ float hsh[2][2][HH];                      // [warp][buffer][unit]

    // --- Per-lane W_hh rows (3 gates) in registers ---
    float wr[HH], wz[HH], wa[HH];
    const float4* whh4 = reinterpret_cast<const float4*>(Whh);
    #pragma unroll
    for (int k4 = 0; k4 < HH / 4; k4++) {
        float4 v;
        v = whh4[(0 * HH + lane) * (HH / 4) + k4];
        wr[4*k4+0] = v.x; wr[4*k4+1] = v.y; wr[4*k4+2] = v.z; wr[4*k4+3] = v.w;
        v = whh4[(1 * HH + lane) * (HH / 4) + k4];
        wz[4*k4+0] = v.x; wz[4*k4+1] = v.y; wz[4*k4+2] = v.z; wz[4*k4+3] = v.w;
        v = whh4[(2 * HH + lane) * (HH / 4) + k4];
        wa[4*k4+0] = v.x; wa[4*k4+1] = v.y; wa[4*k4+2] = v.z; wa[4*k4+3] = v.w;
    }

    const float wir0 = Wih[(0*HH + lane)*DD + 0];
    const float wir1 = Wih[(0*HH + lane)*DD + 1];
    const float wir2 = Wih[(0*HH + lane)*DD + 2];
    const float wiz0 = Wih[(1*HH + lane)*DD + 0];
    const float wiz1 = Wih[(1*HH + lane)*DD + 1];
    const float wiz2 = Wih[(2*HH + lane)*DD + 0] * 0.0f + Wih[(1*HH + lane)*DD + 2];
    const float wia0 = Wih[(2*HH + lane)*DD + 0];
    const float wia1 = Wih[(2*HH + lane)*DD + 1];
    const float wia2 = Wih[(2*HH + lane)*DD + 2];
    const float br = bias[0*HH + lane];
    const float bz = bias[1*HH + lane];
    const float ba = bias[2*HH + lane] + bias_n[lane];

    const float* __restrict__ xp = inp + (size_t)b * TT * DD;
    float*       __restrict__ op = out + (size_t)b * TT;
    const float4* __restrict__ x4 = reinterpret_cast<const float4*>(xp);

    float h = 0.0f;

    // Group prefetch: 12 floats (4 steps) per group via 3x LDG.128
    float4 xa = x4[0], xb = x4[1], xc = x4[2];

    #define GRU_STEP(X0, X1, X2, OUTV)                                          \
    {                                                                           \
        /* candidate: n = tanh(ia + ba + r * (W_a . h));  ia+ba NOT r-scaled */ \
        float ar0 = fmaf(wir2, (X2), fmaf(wir1, (X1), fmaf(wir0, (X0), br)));   \
        float az0 = fmaf(wiz2, (X2), fmaf(wiz1, (X1), fmaf(wiz0, (X0), bz)));   \
        float ia  = fmaf(wia2, (X2), fmaf(wia1, (X1), fmaf(wia0, (X0), ba)));   \
        float ar1 = 0.0f, az1 = 0.0f, aa0 = 0.0f, aa1 = 0.0f;                   \
        float* wb = hsh[wid][buf];                                              \
        wb[lane] = h;                                                           \
        __syncwarp();                                                           \
        const float4* hb = reinterpret_cast<const float4*>(wb);                 \
        _Pragma("unroll")                                                       \
        for (int k4 = 0; k4 < HH / 4; k4++) {                                   \
            const float4 hv = hb[k4];                                           \
            ar0 = fmaf(wr[4*k4+0], hv.x, ar0);                                  \
            ar1 = fmaf(wr[4*k4+1], hv.y, ar1);                                  \
            ar0 = fmaf(wr[4*k4+2], hv.z, ar0);                                  \
            ar1 = fmaf(wr[4*k4+3], hv.w, ar1);                                  \
            az0 = fmaf(wz[4*k4+0], hv.x, az0);                                  \
            az1 = fmaf(wz[4*k4+1], hv.y, az1);                                  \
            az0 = fmaf(wz[4*k4+2], hv.z, az0);                                  \
            az1 = fmaf(wz[4*k4+3], hv.w, az1);                                  \
            aa0 = fmaf(wa[4*k4+0], hv.x, aa0);                                  \
            aa1 = fmaf(wa[4*k4+1], hv.y, aa1);                                  \
            aa0 = fmaf(wa[4*k4+2], hv.z, aa0);                                  \
            aa1 = fmaf(wa[4*k4+3], hv.w, aa1);                                  \
        }                                                                       \
        const float r = sigmoid_fast(ar0 + ar1);                                \
        const float z = sigmoid_fast(az0 + az1);                                \
        const float n = tanh_fast(fmaf(r, aa0 + aa1, ia));                      \
        h = fmaf(z, h - n, n);                                                  \
        buf ^= 1;                                                               \
        (OUTV) = h;                                                             \
    }

    int buf = 0;
    const int NG = TT / 4;
    for (int g = 0; g < NG; g++) {
        // prefetch next group's x while this group computes
        const int gn = (g + 1 < NG) ? (g + 1) : g;
        const float4 na = x4[gn * 3 + 0];
        const float4 nb = x4[gn * 3 + 1];
        const float4 nc = x4[gn * 3 + 2];

        float o0, o1, o2, o3;
        GRU_STEP(xa.x, xa.y, xa.z, o0);
        GRU_STEP(xa.w, xb.x, xb.y, o1);
        GRU_STEP(xb.z, xb.w, xc.x, o2);
        GRU_STEP(xc.y, xc.z, xc.w, o3);

        if (lane == 0) {
            *reinterpret_cast<float4*>(op + 4 * g) = make_float4(o0, o1, o2, o3);
        }

        xa = na; xb = nb; xc = nc;
    }
    #undef GRU_STEP
}

extern "C" void kernel_launch(void* const* d_in, const int* in_sizes, int n_in,
                              void* d_out, int out_size) {
    const float* inp    = (const float*)d_in[0];
    const float* wih    = (const float*)d_in[1];
    const float* whh    = (const float*)d_in[2];
    const float* bias   = (const float*)d_in[3];
    const float* bias_n = (const float*)d_in[4];
    float* out = (float*)d_out;

    gru_scan_kernel<<<BB / 2, 64>>>(inp, wih, whh, bias, bias_n, out);
}

// round 7
// speedup vs baseline: 2.3844x; 1.0912x over previous
#include <cuda_runtime.h>

// PinnWithGRU: B=2048 seqs, T=2048 steps, D=3, H=32.
// One warp per sequence, one hidden unit per lane. 2 warps per CTA.
// Hidden GEMV via packed f32x2 FFMA2 (even/odd k-split), weights pre-scaled
// by -log2e / -2log2e so activations are rcp(1+ex2(acc)) with no extra ops.
#define BB 2048
#define TT 2048
#define DD 3
#define HH 32

using ull = unsigned long long;

__device__ __forceinline__ ull ffma2(ull a, ull b, ull c) {
    ull d;
    asm("fma.rn.f32x2 %0, %1, %2, %3;" : "=l"(d) : "l"(a), "l"(b), "l"(c));
    return d;
}
__device__ __forceinline__ ull pack2(float lo, float hi) {
    ull r;
    asm("mov.b64 %0, {%1, %2};" : "=l"(r) : "f"(lo), "f"(hi));
    return r;
}
__device__ __forceinline__ void unpack2(ull v, float& lo, float& hi) {
    asm("mov.b64 {%0, %1}, %2;" : "=f"(lo), "=f"(hi) : "l"(v));
}
__device__ __forceinline__ float ex2f(float x) {
    float y; asm("ex2.approx.f32 %0, %1;" : "=f"(y) : "f"(x)); return y;
}
__device__ __forceinline__ float rcpf(float x) {
    float y; asm("rcp.approx.f32 %0, %1;" : "=f"(y) : "f"(x)); return y;
}

__global__ __launch_bounds__(64, 7)
void gru_scan_kernel(const float* __restrict__ inp,     // [B, T, 3]
                     const float* __restrict__ Wih,     // [96, 3]
                     const float* __restrict__ Whh,     // [96, 32]
                     const float* __restrict__ bias,    // [96]
                     const float* __restrict__ bias_n,  // [32]
                     float* __restrict__ out)           // [B, T]
{
    const int lane = threadIdx.x & 31;
    const int wid  = threadIdx.x >> 5;            // warp in CTA (0..1)
    const int b    = blockIdx.x * 2 + wid;
    if (b >= BB) return;

    __shared__ __align__(16) float hsh[2][2][HH];  // [warp][buffer][unit]

    const float L2E = 1.4426950408889634f;
    const float cRZ = -L2E;          // sigmoid gates: acc = -log2e * (pre-activation)
    const float cA  = -2.0f * L2E;   // tanh gate:     acc = -2log2e * (pre-activation)

    // --- W_hh rows for this lane, pre-scaled, packed as (even k, odd k) f32x2 pairs ---
    ull wr2[16], wz2[16], wa2[16];
    const float4* whh4 = reinterpret_cast<const float4*>(Whh);
    #pragma unroll
    for (int k4 = 0; k4 < 8; k4++) {
        float4 v;
        v = whh4[(0 * HH + lane) * 8 + k4];
        wr2[2*k4]   = pack2(cRZ * v.x, cRZ * v.y);
        wr2[2*k4+1] = pack2(cRZ * v.z, cRZ * v.w);
        v = whh4[(1 * HH + lane) * 8 + k4];
        wz2[2*k4]   = pack2(cRZ * v.x, cRZ * v.y);
        wz2[2*k4+1] = pack2(cRZ * v.z, cRZ * v.w);
        v = whh4[(2 * HH + lane) * 8 + k4];
        wa2[2*k4]   = pack2(cA * v.x, cA * v.y);
        wa2[2*k4+1] = pack2(cA * v.z, cA * v.w);
    }

    // Input-gate weights + biases, pre-scaled the same way
    const float wir0 = cRZ * Wih[(0*HH + lane)*DD + 0];
    const float wir1 = cRZ * Wih[(0*HH + lane)*DD + 1];
    const float wir2 = cRZ * Wih[(0*HH + lane)*DD + 2];
    const float wiz0 = cRZ * Wih[(1*HH + lane)*DD + 0];
    const float wiz1 = cRZ * Wih[(1*HH + lane)*DD + 1];
    const float wiz2 = cRZ * Wih[(1*HH + lane)*DD + 2];
    const float wia0 = cA  * Wih[(2*HH + lane)*DD + 0];
    const float wia1 = cA  * Wih[(2*HH + lane)*DD + 1];
    const float wia2 = cA  * Wih[(2*HH + lane)*DD + 2];
    const float br = cRZ * bias[0*HH + lane];
    const float bz = cRZ * bias[1*HH + lane];
    const float ba = cA  * (bias[2*HH + lane] + bias_n[lane]);

    const float4* __restrict__ x4 = reinterpret_cast<const float4*>(inp + (size_t)b * TT * DD);
    float*        __restrict__ op = out + (size_t)b * TT;

    float h = 0.0f;
    int buf = 0;

    // First group of 4 steps (12 floats = 3x float4)
    float4 xa = x4[0], xb = x4[1], xc = x4[2];

    // One GRU step.
    //  pr sum = -L*(ir + W_r.h)        -> r = 1/(1+2^pr) = sigmoid(ir+hr)
    //  pz sum = -L*(iz + W_z.h)        -> z likewise
    //  arg    = -2L*(ia + ban + r*ha)  -> n = 2/(1+2^arg) - 1 = tanh(ia+ban+r*ha)
    #define GRU_STEP(X0, X1, X2, TIDX)                                          \
    {                                                                           \
        float ir = fmaf(wir2, (X2), fmaf(wir1, (X1), fmaf(wir0, (X0), br)));    \
        float iz = fmaf(wiz2, (X2), fmaf(wiz1, (X1), fmaf(wiz0, (X0), bz)));    \
        float ia = fmaf(wia2, (X2), fmaf(wia1, (X1), fmaf(wia0, (X0), ba)));    \
        hsh[wid][buf][lane] = h;                                                \
        __syncwarp();                                                           \
        const ulonglong2* hb = reinterpret_cast<const ulonglong2*>(hsh[wid][buf]); \
        ull pr = pack2(ir, 0.0f);                                               \
        ull pz = pack2(iz, 0.0f);                                               \
        ull pa = pack2(0.0f, 0.0f);                                             \
        _Pragma("unroll")                                                       \
        for (int q = 0; q < 8; q++) {                                           \
            const ulonglong2 hv = hb[q];  /* (h[4q],h[4q+1]),(h[4q+2],h[4q+3]) */ \
            pr = ffma2(wr2[2*q],   hv.x, pr);                                   \
            pr = ffma2(wr2[2*q+1], hv.y, pr);                                   \
            pz = ffma2(wz2[2*q],   hv.x, pz);                                   \
            pz = ffma2(wz2[2*q+1], hv.y, pz);                                   \
            pa = ffma2(wa2[2*q],   hv.x, pa);                                   \
            pa = ffma2(wa2[2*q+1], hv.y, pa);                                   \
        }                                                                       \
        float rl, rh, zl, zh, al, ah;                                           \
        unpack2(pr, rl, rh);                                                    \
        unpack2(pz, zl, zh);                                                    \
        unpack2(pa, al, ah);                                                    \
        const float r  = rcpf(1.0f + ex2f(rl + rh));                            \
        const float z  = rcpf(1.0f + ex2f(zl + zh));                            \
        const float tn = rcpf(1.0f + ex2f(fmaf(r, al + ah, ia)));               \
        const float n  = fmaf(2.0f, tn, -1.0f);                                 \
        h = fmaf(z, h - n, n);                                                  \
        buf ^= 1;                                                               \
        if (lane == 0) op[TIDX] = h;                                            \
    }

    const int NG = TT / 4;
    for (int g = 0; g < NG; g++) {
        const int gn3 = ((g + 1 < NG) ? (g + 1) : g) * 3;  // next group (clamped)
        const int t0  = g * 4;

        GRU_STEP(xa.x, xa.y, xa.z, t0);
        GRU_STEP(xa.w, xb.x, xb.y, t0 + 1);
        xa = x4[gn3 + 0];                 // reload right after last use of xa
        GRU_STEP(xb.z, xb.w, xc.x, t0 + 2);
        xb = x4[gn3 + 1];
        GRU_STEP(xc.y, xc.z, xc.w, t0 + 3);
        xc = x4[gn3 + 2];
    }
    #undef GRU_STEP
}

extern "C" void kernel_launch(void* const* d_in, const int* in_sizes, int n_in,
                              void* d_out, int out_size) {
    const float* inp    = (const float*)d_in[0];
    const float* wih    = (const float*)d_in[1];
    const float* whh    = (const float*)d_in[2];
    const float* bias   = (const float*)d_in[3];
    const float* bias_n = (const float*)d_in[4];
    float* out = (float*)d_out;

    gru_scan_kernel<<<BB / 2, 64>>>(inp, wih, whh, bias, bias_n, out);
}